// round 13
// baseline (speedup 1.0000x reference)
#include <cuda_runtime.h>
#include <cuda_bf16.h>
#include <cstdint>

#define NODES 100000
#define EDGES 1600000
#define D 32
#define LAYERS 3
#define HOPS 3

#define SCAN_B 512

// ---------------- scratch (device globals) ----------------
__device__ float g_tmp3[NODES * 3];               // [deg | count | fill] one memset
__device__ unsigned long long g_scanstate[256];   // decoupled-lookback state
__device__ int   g_rowptr[NODES + 1];
__device__ __align__(16) int2 g_epack[EDGES];     // (row*128 byte-offset, norm bits), grouped by col
__device__ float g_g1[NODES * D];
__device__ float g_g2[NODES * D];
__device__ float g_g3[NODES * D];
__device__ float g_x[NODES * D];

// ---------------- f32x2 helpers ----------------
__device__ __forceinline__ unsigned long long pack2(float a, float b) {
    unsigned long long r;
    asm("mov.b64 %0, {%1, %2};" : "=l"(r) : "f"(a), "f"(b));
    return r;
}
__device__ __forceinline__ float2 unpack2(unsigned long long v) {
    float2 r;
    asm("mov.b64 {%0, %1}, %2;" : "=f"(r.x), "=f"(r.y) : "l"(v));
    return r;
}
__device__ __forceinline__ void fma2(unsigned long long& d,
                                     unsigned long long a, unsigned long long b) {
    asm("fma.rn.f32x2 %0, %1, %2, %0;" : "+l"(d) : "l"(a), "l"(b));
}

__device__ __forceinline__ float ld_off(const char* base, int byteoff) {
    return *reinterpret_cast<const float*>(base + byteoff);
}

// ---------------- setup kernels ----------------

__global__ void deg_kernel(const int* __restrict__ col, const float* __restrict__ ew, int E)
{
    int e = blockIdx.x * blockDim.x + threadIdx.x;
    if (e < E) {
        int c = col[e];
        atomicAdd(&g_tmp3[c], ew[e]);                                  // deg (raw)
        atomicAdd(reinterpret_cast<int*>(g_tmp3 + NODES) + c, 1);      // count
    }
}

// single-pass exclusive scan of count -> rowptr, decoupled lookback across blocks
__global__ void scanfused_kernel(int N, int E)
{
    __shared__ int sh[SCAN_B];
    __shared__ int s_prefix;
    const int* cnt = reinterpret_cast<const int*>(g_tmp3 + NODES);
    int t = threadIdx.x, b = blockIdx.x;
    int i = b * SCAN_B + t;
    int v = (i < N) ? cnt[i] : 0;
    sh[t] = v;
    __syncthreads();
#pragma unroll
    for (int off = 1; off < SCAN_B; off <<= 1) {
        int add = (t >= off) ? sh[t - off] : 0;
        __syncthreads();
        sh[t] += add;
        __syncthreads();
    }
    int incl = sh[t];
    int total = sh[SCAN_B - 1];

    if (t == 0) {
        unsigned long long flag = (b == 0) ? 2ull : 1ull;
        atomicExch(&g_scanstate[b], (flag << 32) | (unsigned)total);
        int prefix = 0;
        if (b > 0) {
            int j = b - 1;
            while (true) {
                unsigned long long s;
                do { s = atomicAdd(&g_scanstate[j], 0ull); } while ((s >> 32) == 0ull);
                prefix += (int)(unsigned)s;
                if ((s >> 32) == 2ull) break;
                j--;
            }
            atomicExch(&g_scanstate[b], (2ull << 32) | (unsigned)(prefix + total));
        }
        s_prefix = prefix;
    }
    __syncthreads();
    if (i < N) g_rowptr[i] = s_prefix + incl - v;
    if (i == N) g_rowptr[N] = E;
}

// scatter edges into CSR slots grouped by col; norm inline; store BYTE OFFSET of row
__global__ void fill_kernel(const int* __restrict__ row, const int* __restrict__ col,
                            const float* __restrict__ ew, int E)
{
    int* fill = reinterpret_cast<int*>(g_tmp3 + 2 * NODES);
    int e = blockIdx.x * blockDim.x + threadIdx.x;
    if (e < E) {
        int r = row[e];
        int c = col[e];
        float dr = g_tmp3[r];
        float dc = g_tmp3[c];
        float sr = (dr > 0.0f) ? rsqrtf(dr) : 0.0f;
        float sc = (dc > 0.0f) ? rsqrtf(dc) : 0.0f;
        float w = sr * ew[e] * sc;
        int p = g_rowptr[c] + atomicAdd(&fill[c], 1);
        g_epack[p] = make_int2(r << 7, __float_as_int(w));   // byte offset of h row
    }
}

// ---------------- pure gather: dst[n,:] = sum_e norm_e * h[row_e,:] ----------------
// epack.x is the byte offset of the source row. 4-pair batched inner loop.
__global__ void gather_kernel(float* __restrict__ dst, const float* __restrict__ h, int N)
{
    int gt = blockIdx.x * blockDim.x + threadIdx.x;
    int n = gt >> 5;
    int lane = gt & 31;
    if (n >= N) return;

    const char* hb = reinterpret_cast<const char*>(h) + lane * 4;

    int s = g_rowptr[n];
    int e = g_rowptr[n + 1];
    float a0 = 0.0f, a1 = 0.0f, a2 = 0.0f, a3 = 0.0f;

    int i = s;
    if ((i & 1) && i < e) {
        int2 t = g_epack[i];
        a0 = fmaf(__int_as_float(t.y), ld_off(hb, t.x), a0);
        i++;
    }
    int npair = (e - i) >> 1;
    const int4* pp = reinterpret_cast<const int4*>(g_epack + i);

    // batches of 4 pairs (8 edges): front-load all edge data, then all h loads, then FMAs
    int nb4 = npair >> 2;
    for (int bb = 0; bb < nb4; bb++) {
        int4 t0 = pp[bb * 4 + 0];
        int4 t1 = pp[bb * 4 + 1];
        int4 t2 = pp[bb * 4 + 2];
        int4 t3 = pp[bb * 4 + 3];
        float v0 = ld_off(hb, t0.x);
        float v1 = ld_off(hb, t0.z);
        float v2 = ld_off(hb, t1.x);
        float v3 = ld_off(hb, t1.z);
        float v4 = ld_off(hb, t2.x);
        float v5 = ld_off(hb, t2.z);
        float v6 = ld_off(hb, t3.x);
        float v7 = ld_off(hb, t3.z);
        a0 = fmaf(__int_as_float(t0.y), v0, a0);
        a1 = fmaf(__int_as_float(t0.w), v1, a1);
        a2 = fmaf(__int_as_float(t1.y), v2, a2);
        a3 = fmaf(__int_as_float(t1.w), v3, a3);
        a0 = fmaf(__int_as_float(t2.y), v4, a0);
        a1 = fmaf(__int_as_float(t2.w), v5, a1);
        a2 = fmaf(__int_as_float(t3.y), v6, a2);
        a3 = fmaf(__int_as_float(t3.w), v7, a3);
    }
    // leftover pairs
    for (int p = nb4 * 4; p < npair; p++) {
        int4 t = pp[p];
        float v0 = ld_off(hb, t.x);
        float v1 = ld_off(hb, t.z);
        a0 = fmaf(__int_as_float(t.y), v0, a0);
        a1 = fmaf(__int_as_float(t.w), v1, a1);
    }
    i += npair * 2;
    if (i < e) {
        int2 t = g_epack[i];
        a0 = fmaf(__int_as_float(t.y), ld_off(hb, t.x), a0);
    }

    dst[(size_t)n * D + lane] = (a0 + a1) + (a2 + a3);
}

// ---------------- quadgemm: dst[n,:] = relu( sum_m h_m[n,:] @ W4[m]  + bias ) ------
__global__ __launch_bounds__(256, 2)
void quadgemm_kernel(float* __restrict__ dst,
                     const float* __restrict__ h0, const float* __restrict__ h1,
                     const float* __restrict__ h2, const float* __restrict__ h3,
                     const float* __restrict__ W4, const float* __restrict__ bias,
                     int N)
{
    __shared__ __align__(16) float Ws[4 * D * D];   // 16 KB
    __shared__ float Bs[D];
    int t = threadIdx.x;
#pragma unroll
    for (int q = 0; q < 4; q++)
        reinterpret_cast<float4*>(Ws)[q * 256 + t] =
            reinterpret_cast<const float4*>(W4)[q * 256 + t];
    if (t < D) Bs[t] = bias[t];
    __syncthreads();

    int n = blockIdx.x * 256 + t;
    if (n >= N) return;

    unsigned long long acc[D / 2];
#pragma unroll
    for (int j = 0; j < D / 2; j++) acc[j] = 0ull;

    const float* hs[4] = { h0, h1, h2, h3 };

#pragma unroll
    for (int m = 0; m < 4; m++) {
        float h[D];
        const float4* hr = reinterpret_cast<const float4*>(hs[m] + (size_t)n * D);
#pragma unroll
        for (int q = 0; q < 8; q++) {
            float4 v = __ldg(hr + q);
            h[q*4] = v.x; h[q*4+1] = v.y; h[q*4+2] = v.z; h[q*4+3] = v.w;
        }
        const ulonglong2* Wm = reinterpret_cast<const ulonglong2*>(Ws + m * D * D);
#pragma unroll
        for (int i = 0; i < D; i++) {
            unsigned long long hv = pack2(h[i], h[i]);
            const ulonglong2* wr = Wm + i * 8;
#pragma unroll
            for (int j = 0; j < 8; j++) {
                ulonglong2 w = wr[j];
                fma2(acc[j*2],     hv, w.x);
                fma2(acc[j*2 + 1], hv, w.y);
            }
        }
    }

    float* drow = dst + (size_t)n * D;
#pragma unroll
    for (int j2 = 0; j2 < D / 4; j2++) {
        float2 a = unpack2(acc[j2*2]);
        float2 b = unpack2(acc[j2*2 + 1]);
        float4 o;
        o.x = fmaxf(a.x + Bs[j2*4],     0.0f);
        o.y = fmaxf(a.y + Bs[j2*4 + 1], 0.0f);
        o.z = fmaxf(b.x + Bs[j2*4 + 2], 0.0f);
        o.w = fmaxf(b.y + Bs[j2*4 + 3], 0.0f);
        reinterpret_cast<float4*>(drow)[j2] = o;
    }
}

// ---------------- launch ----------------

extern "C" void kernel_launch(void* const* d_in, const int* in_sizes, int n_in,
                              void* d_out, int out_size)
{
    const float* x  = (const float*)d_in[0];
    const int*   ei = (const int*)d_in[1];
    const float* ew = (const float*)d_in[2];
    const float* W  = (const float*)d_in[3];
    const float* b  = (const float*)d_in[4];

    const int N = in_sizes[0] / D;
    const int E = in_sizes[2];

    const int* row = ei;
    const int* col = ei + E;

    float* tmp3_p;  cudaGetSymbolAddress((void**)&tmp3_p,  g_tmp3);
    void*  scan_p;  cudaGetSymbolAddress(&scan_p,          g_scanstate);
    float* g1_p;    cudaGetSymbolAddress((void**)&g1_p,    g_g1);
    float* g2_p;    cudaGetSymbolAddress((void**)&g2_p,    g_g2);
    float* g3_p;    cudaGetSymbolAddress((void**)&g3_p,    g_g3);
    float* x_p;     cudaGetSymbolAddress((void**)&x_p,     g_x);

    const int TB = 256;
    const int eb = (E + TB - 1) / TB;
    const int scan_blocks = (N + SCAN_B - 1) / SCAN_B;

    // ---- CSR + norm build ----
    cudaMemsetAsync(tmp3_p, 0, (size_t)3 * N * sizeof(float));
    cudaMemsetAsync(scan_p, 0, 256 * sizeof(unsigned long long));
    deg_kernel<<<eb, TB>>>(col, ew, E);
    scanfused_kernel<<<scan_blocks, SCAN_B>>>(N, E);
    fill_kernel<<<eb, TB>>>(row, col, ew, E);

    const int qg_blocks     = (N + 255) / 256;
    const int gather_blocks = (N * 32 + TB - 1) / TB;

    const float* xcur = x;
    for (int l = 0; l < LAYERS; l++) {
        const float* Wl = W + (size_t)l * (HOPS + 1) * D * D;

        // power form: g1 = A x, g2 = A g1, g3 = A g2
        gather_kernel<<<gather_blocks, TB>>>(g1_p, xcur, N);
        gather_kernel<<<gather_blocks, TB>>>(g2_p, g1_p, N);
        gather_kernel<<<gather_blocks, TB>>>(g3_p, g2_p, N);

        float* dst = (l == LAYERS - 1) ? (float*)d_out : x_p;
        // x' = relu(x W0 + g1 W1 + g2 W2 + g3 W3 + b)
        quadgemm_kernel<<<qg_blocks, 256>>>(dst, xcur, g1_p, g2_p, g3_p,
                                            Wl, b + (size_t)l * D, N);
        xcur = x_p;
    }
}

// round 14
// speedup vs baseline: 1.0898x; 1.0898x over previous
#include <cuda_runtime.h>
#include <cuda_bf16.h>
#include <cstdint>

#define NODES 100000
#define EDGES 1600000
#define D 32
#define LAYERS 3
#define HOPS 3

#define SCAN_B 512

// ---------------- scratch (device globals) ----------------
__device__ float g_tmp3[NODES * 3];               // [deg | count | fill] one memset
__device__ unsigned long long g_scanstate[256];   // decoupled-lookback state
__device__ int   g_rowptr[NODES + 1];
__device__ __align__(16) int2 g_epack[EDGES];     // (row*128 byte-offset, norm bits), grouped by col
__device__ float g_g1[NODES * D];
__device__ float g_g2[NODES * D];
__device__ float g_g3[NODES * D];
__device__ float g_x[NODES * D];

// ---------------- f32x2 helpers ----------------
__device__ __forceinline__ unsigned long long pack2(float a, float b) {
    unsigned long long r;
    asm("mov.b64 %0, {%1, %2};" : "=l"(r) : "f"(a), "f"(b));
    return r;
}
__device__ __forceinline__ float2 unpack2(unsigned long long v) {
    float2 r;
    asm("mov.b64 {%0, %1}, %2;" : "=f"(r.x), "=f"(r.y) : "l"(v));
    return r;
}
__device__ __forceinline__ void fma2(unsigned long long& d,
                                     unsigned long long a, unsigned long long b) {
    asm("fma.rn.f32x2 %0, %1, %2, %0;" : "+l"(d) : "l"(a), "l"(b));
}

__device__ __forceinline__ float ld_off(const char* base, int byteoff) {
    return __ldg(reinterpret_cast<const float*>(base + byteoff));
}

// streaming int4 load (evict-first; keep L1 for h rows)
__device__ __forceinline__ int4 ldcs_int4(const int4* p) {
    return __ldcs(p);
}

// ---------------- setup kernels ----------------

__global__ void deg_kernel(const int* __restrict__ col, const float* __restrict__ ew, int E)
{
    int e = blockIdx.x * blockDim.x + threadIdx.x;
    if (e < E) {
        int c = col[e];
        atomicAdd(&g_tmp3[c], ew[e]);                                  // deg (raw)
        atomicAdd(reinterpret_cast<int*>(g_tmp3 + NODES) + c, 1);      // count
    }
}

// single-pass exclusive scan of count -> rowptr, decoupled lookback across blocks
__global__ void scanfused_kernel(int N, int E)
{
    __shared__ int sh[SCAN_B];
    __shared__ int s_prefix;
    const int* cnt = reinterpret_cast<const int*>(g_tmp3 + NODES);
    int t = threadIdx.x, b = blockIdx.x;
    int i = b * SCAN_B + t;
    int v = (i < N) ? cnt[i] : 0;
    sh[t] = v;
    __syncthreads();
#pragma unroll
    for (int off = 1; off < SCAN_B; off <<= 1) {
        int add = (t >= off) ? sh[t - off] : 0;
        __syncthreads();
        sh[t] += add;
        __syncthreads();
    }
    int incl = sh[t];
    int total = sh[SCAN_B - 1];

    if (t == 0) {
        unsigned long long flag = (b == 0) ? 2ull : 1ull;
        atomicExch(&g_scanstate[b], (flag << 32) | (unsigned)total);
        int prefix = 0;
        if (b > 0) {
            int j = b - 1;
            while (true) {
                unsigned long long s;
                do { s = atomicAdd(&g_scanstate[j], 0ull); } while ((s >> 32) == 0ull);
                prefix += (int)(unsigned)s;
                if ((s >> 32) == 2ull) break;
                j--;
            }
            atomicExch(&g_scanstate[b], (2ull << 32) | (unsigned)(prefix + total));
        }
        s_prefix = prefix;
    }
    __syncthreads();
    if (i < N) g_rowptr[i] = s_prefix + incl - v;
    if (i == N) g_rowptr[N] = E;
}

// scatter edges into CSR slots grouped by col; norm inline; store BYTE OFFSET of row
__global__ void fill_kernel(const int* __restrict__ row, const int* __restrict__ col,
                            const float* __restrict__ ew, int E)
{
    int* fill = reinterpret_cast<int*>(g_tmp3 + 2 * NODES);
    int e = blockIdx.x * blockDim.x + threadIdx.x;
    if (e < E) {
        int r = row[e];
        int c = col[e];
        float dr = g_tmp3[r];
        float dc = g_tmp3[c];
        float sr = (dr > 0.0f) ? rsqrtf(dr) : 0.0f;
        float sc = (dc > 0.0f) ? rsqrtf(dc) : 0.0f;
        float w = sr * ew[e] * sc;
        int p = g_rowptr[c] + atomicAdd(&fill[c], 1);
        g_epack[p] = make_int2(r << 7, __float_as_int(w));   // byte offset of h row
    }
}

// ---------------- pure gather: dst[n,:] = sum_e norm_e * h[row_e,:] ----------------
// Round-12 loop structure (unroll 8, dual acc) + byte-offset epack + streaming epack loads.
__global__ void gather_kernel(float* __restrict__ dst, const float* __restrict__ h, int N)
{
    int gt = blockIdx.x * blockDim.x + threadIdx.x;
    int n = gt >> 5;
    int lane = gt & 31;
    if (n >= N) return;

    const char* hb = reinterpret_cast<const char*>(h) + lane * 4;

    int s = g_rowptr[n];
    int e = g_rowptr[n + 1];
    float acc0 = 0.0f, acc1 = 0.0f;

    int i = s;
    if ((i & 1) && i < e) {
        int2 t = g_epack[i];
        acc0 = fmaf(__int_as_float(t.y), ld_off(hb, t.x), acc0);
        i++;
    }
    int npair = (e - i) >> 1;
    const int4* pp = reinterpret_cast<const int4*>(g_epack + i);
#pragma unroll 8
    for (int p = 0; p < npair; p++) {
        int4 t = ldcs_int4(pp + p);
        float v0 = ld_off(hb, t.x);
        float v1 = ld_off(hb, t.z);
        acc0 = fmaf(__int_as_float(t.y), v0, acc0);
        acc1 = fmaf(__int_as_float(t.w), v1, acc1);
    }
    i += npair * 2;
    if (i < e) {
        int2 t = g_epack[i];
        acc0 = fmaf(__int_as_float(t.y), ld_off(hb, t.x), acc0);
    }

    dst[(size_t)n * D + lane] = acc0 + acc1;
}

// ---------------- quadgemm: dst[n,:] = relu( sum_m h_m[n,:] @ W4[m]  + bias ) ------
__global__ __launch_bounds__(256, 2)
void quadgemm_kernel(float* __restrict__ dst,
                     const float* __restrict__ h0, const float* __restrict__ h1,
                     const float* __restrict__ h2, const float* __restrict__ h3,
                     const float* __restrict__ W4, const float* __restrict__ bias,
                     int N)
{
    __shared__ __align__(16) float Ws[4 * D * D];   // 16 KB
    __shared__ float Bs[D];
    int t = threadIdx.x;
#pragma unroll
    for (int q = 0; q < 4; q++)
        reinterpret_cast<float4*>(Ws)[q * 256 + t] =
            reinterpret_cast<const float4*>(W4)[q * 256 + t];
    if (t < D) Bs[t] = bias[t];
    __syncthreads();

    int n = blockIdx.x * 256 + t;
    if (n >= N) return;

    unsigned long long acc[D / 2];
#pragma unroll
    for (int j = 0; j < D / 2; j++) acc[j] = 0ull;

    const float* hs[4] = { h0, h1, h2, h3 };

#pragma unroll
    for (int m = 0; m < 4; m++) {
        float h[D];
        const float4* hr = reinterpret_cast<const float4*>(hs[m] + (size_t)n * D);
#pragma unroll
        for (int q = 0; q < 8; q++) {
            float4 v = __ldg(hr + q);
            h[q*4] = v.x; h[q*4+1] = v.y; h[q*4+2] = v.z; h[q*4+3] = v.w;
        }
        const ulonglong2* Wm = reinterpret_cast<const ulonglong2*>(Ws + m * D * D);
#pragma unroll
        for (int i = 0; i < D; i++) {
            unsigned long long hv = pack2(h[i], h[i]);
            const ulonglong2* wr = Wm + i * 8;
#pragma unroll
            for (int j = 0; j < 8; j++) {
                ulonglong2 w = wr[j];
                fma2(acc[j*2],     hv, w.x);
                fma2(acc[j*2 + 1], hv, w.y);
            }
        }
    }

    float* drow = dst + (size_t)n * D;
#pragma unroll
    for (int j2 = 0; j2 < D / 4; j2++) {
        float2 a = unpack2(acc[j2*2]);
        float2 b = unpack2(acc[j2*2 + 1]);
        float4 o;
        o.x = fmaxf(a.x + Bs[j2*4],     0.0f);
        o.y = fmaxf(a.y + Bs[j2*4 + 1], 0.0f);
        o.z = fmaxf(b.x + Bs[j2*4 + 2], 0.0f);
        o.w = fmaxf(b.y + Bs[j2*4 + 3], 0.0f);
        reinterpret_cast<float4*>(drow)[j2] = o;
    }
}

// ---------------- launch ----------------

extern "C" void kernel_launch(void* const* d_in, const int* in_sizes, int n_in,
                              void* d_out, int out_size)
{
    const float* x  = (const float*)d_in[0];
    const int*   ei = (const int*)d_in[1];
    const float* ew = (const float*)d_in[2];
    const float* W  = (const float*)d_in[3];
    const float* b  = (const float*)d_in[4];

    const int N = in_sizes[0] / D;
    const int E = in_sizes[2];

    const int* row = ei;
    const int* col = ei + E;

    float* tmp3_p;  cudaGetSymbolAddress((void**)&tmp3_p,  g_tmp3);
    void*  scan_p;  cudaGetSymbolAddress(&scan_p,          g_scanstate);
    float* g1_p;    cudaGetSymbolAddress((void**)&g1_p,    g_g1);
    float* g2_p;    cudaGetSymbolAddress((void**)&g2_p,    g_g2);
    float* g3_p;    cudaGetSymbolAddress((void**)&g3_p,    g_g3);
    float* x_p;     cudaGetSymbolAddress((void**)&x_p,     g_x);

    const int TB = 256;
    const int eb = (E + TB - 1) / TB;
    const int scan_blocks = (N + SCAN_B - 1) / SCAN_B;

    // ---- CSR + norm build ----
    cudaMemsetAsync(tmp3_p, 0, (size_t)3 * N * sizeof(float));
    cudaMemsetAsync(scan_p, 0, 256 * sizeof(unsigned long long));
    deg_kernel<<<eb, TB>>>(col, ew, E);
    scanfused_kernel<<<scan_blocks, SCAN_B>>>(N, E);
    fill_kernel<<<eb, TB>>>(row, col, ew, E);

    const int qg_blocks     = (N + 255) / 256;
    const int gather_blocks = (N * 32 + TB - 1) / TB;

    const float* xcur = x;
    for (int l = 0; l < LAYERS; l++) {
        const float* Wl = W + (size_t)l * (HOPS + 1) * D * D;

        // power form: g1 = A x, g2 = A g1, g3 = A g2
        gather_kernel<<<gather_blocks, TB>>>(g1_p, xcur, N);
        gather_kernel<<<gather_blocks, TB>>>(g2_p, g1_p, N);
        gather_kernel<<<gather_blocks, TB>>>(g3_p, g2_p, N);

        float* dst = (l == LAYERS - 1) ? (float*)d_out : x_p;
        // x' = relu(x W0 + g1 W1 + g2 W2 + g3 W3 + b)
        quadgemm_kernel<<<qg_blocks, 256>>>(dst, xcur, g1_p, g2_p, g3_p,
                                            Wl, b + (size_t)l * D, N);
        xcur = x_p;
    }
}

// round 16
// speedup vs baseline: 1.2771x; 1.1719x over previous
#include <cuda_runtime.h>
#include <cuda_bf16.h>
#include <cstdint>

#define NODES 100000
#define EDGES 1600000
#define D 32
#define LAYERS 3
#define HOPS 3

#define SCAN_B 512

// ---------------- scratch (device globals) ----------------
__device__ float g_tmp3[NODES * 3];               // [deg | count | fill] one memset
__device__ unsigned long long g_scanstate[256];   // decoupled-lookback state
__device__ int   g_rowptr[NODES + 1];
__device__ __align__(16) int2 g_epack[EDGES];     // (row*128 byte-offset, norm bits), grouped by col
__device__ float g_g1[NODES * D];
__device__ float g_g2[NODES * D];
__device__ float g_g3[NODES * D];
__device__ float g_x[NODES * D];

// ---------------- f32x2 helpers ----------------
__device__ __forceinline__ unsigned long long pack2(float a, float b) {
    unsigned long long r;
    asm("mov.b64 %0, {%1, %2};" : "=l"(r) : "f"(a), "f"(b));
    return r;
}
__device__ __forceinline__ float2 unpack2(unsigned long long v) {
    float2 r;
    asm("mov.b64 {%0, %1}, %2;" : "=f"(r.x), "=f"(r.y) : "l"(v));
    return r;
}
__device__ __forceinline__ void fma2(unsigned long long& d,
                                     unsigned long long a, unsigned long long b) {
    asm("fma.rn.f32x2 %0, %1, %2, %0;" : "+l"(d) : "l"(a), "l"(b));
}

// ---------------- setup kernels ----------------

__global__ void deg_kernel(const int* __restrict__ col, const float* __restrict__ ew, int E)
{
    int e = blockIdx.x * blockDim.x + threadIdx.x;
    if (e < E) {
        int c = col[e];
        atomicAdd(&g_tmp3[c], ew[e]);                                  // deg (raw)
        atomicAdd(reinterpret_cast<int*>(g_tmp3 + NODES) + c, 1);      // count
    }
}

// single-pass exclusive scan of count -> rowptr, decoupled lookback across blocks
__global__ void scanfused_kernel(int N, int E)
{
    __shared__ int sh[SCAN_B];
    __shared__ int s_prefix;
    const int* cnt = reinterpret_cast<const int*>(g_tmp3 + NODES);
    int t = threadIdx.x, b = blockIdx.x;
    int i = b * SCAN_B + t;
    int v = (i < N) ? cnt[i] : 0;
    sh[t] = v;
    __syncthreads();
#pragma unroll
    for (int off = 1; off < SCAN_B; off <<= 1) {
        int add = (t >= off) ? sh[t - off] : 0;
        __syncthreads();
        sh[t] += add;
        __syncthreads();
    }
    int incl = sh[t];
    int total = sh[SCAN_B - 1];

    if (t == 0) {
        unsigned long long flag = (b == 0) ? 2ull : 1ull;
        atomicExch(&g_scanstate[b], (flag << 32) | (unsigned)total);
        int prefix = 0;
        if (b > 0) {
            int j = b - 1;
            while (true) {
                unsigned long long s;
                do { s = atomicAdd(&g_scanstate[j], 0ull); } while ((s >> 32) == 0ull);
                prefix += (int)(unsigned)s;
                if ((s >> 32) == 2ull) break;
                j--;
            }
            atomicExch(&g_scanstate[b], (2ull << 32) | (unsigned)(prefix + total));
        }
        s_prefix = prefix;
    }
    __syncthreads();
    if (i < N) g_rowptr[i] = s_prefix + incl - v;
    if (i == N) g_rowptr[N] = E;
}

// scatter edges into CSR slots grouped by col; norm inline; store BYTE OFFSET of row
__global__ void fill_kernel(const int* __restrict__ row, const int* __restrict__ col,
                            const float* __restrict__ ew, int E)
{
    int* fill = reinterpret_cast<int*>(g_tmp3 + 2 * NODES);
    int e = blockIdx.x * blockDim.x + threadIdx.x;
    if (e < E) {
        int r = row[e];
        int c = col[e];
        float dr = g_tmp3[r];
        float dc = g_tmp3[c];
        float sr = (dr > 0.0f) ? rsqrtf(dr) : 0.0f;
        float sc = (dc > 0.0f) ? rsqrtf(dc) : 0.0f;
        float w = sr * ew[e] * sc;
        int p = g_rowptr[c] + atomicAdd(&fill[c], 1);
        g_epack[p] = make_int2(r << 7, __float_as_int(w));   // byte offset of h row
    }
}

// ---------------- pure gather: dst[n,:] = sum_e norm_e * h[row_e,:] ----------------
// 4 nodes per warp, 8 lanes per node, 16 bytes (float4) per lane via f32x2 math.
__global__ void gather_kernel(float* __restrict__ dst, const float* __restrict__ h, int N)
{
    int gt = blockIdx.x * blockDim.x + threadIdx.x;
    int warp = gt >> 5;
    int lane = gt & 31;
    int q  = lane >> 3;       // node slot within warp (0..3)
    int ql = lane & 7;        // float4 slot within row (0..7)
    int n = warp * 4 + q;
    if (n >= N) return;

    const char* hb = reinterpret_cast<const char*>(h) + ql * 16;

    int s = g_rowptr[n];
    int e = g_rowptr[n + 1];
    unsigned long long a0 = 0ull, a1 = 0ull;   // even edges, f32x2 pair (lo, hi)
    unsigned long long b0 = 0ull, b1 = 0ull;   // odd edges

    int i = s;
    if ((i & 1) && i < e) {
        int2 t = g_epack[i];
        ulonglong2 v = *reinterpret_cast<const ulonglong2*>(hb + t.x);
        unsigned long long w = pack2(__int_as_float(t.y), __int_as_float(t.y));
        fma2(a0, w, v.x);
        fma2(a1, w, v.y);
        i++;
    }
    int npair = (e - i) >> 1;
    const int4* pp = reinterpret_cast<const int4*>(g_epack + i);
#pragma unroll 4
    for (int p = 0; p < npair; p++) {
        int4 t = __ldcs(pp + p);
        ulonglong2 v0 = *reinterpret_cast<const ulonglong2*>(hb + t.x);
        ulonglong2 v1 = *reinterpret_cast<const ulonglong2*>(hb + t.z);
        unsigned long long w0 = pack2(__int_as_float(t.y), __int_as_float(t.y));
        unsigned long long w1 = pack2(__int_as_float(t.w), __int_as_float(t.w));
        fma2(a0, w0, v0.x);
        fma2(a1, w0, v0.y);
        fma2(b0, w1, v1.x);
        fma2(b1, w1, v1.y);
    }
    i += npair * 2;
    if (i < e) {
        int2 t = g_epack[i];
        ulonglong2 v = *reinterpret_cast<const ulonglong2*>(hb + t.x);
        unsigned long long w = pack2(__int_as_float(t.y), __int_as_float(t.y));
        fma2(b0, w, v.x);
        fma2(b1, w, v.y);
    }

    float2 r0 = unpack2(a0), r1 = unpack2(b0);
    float2 r2 = unpack2(a1), r3 = unpack2(b1);
    float4 out;
    out.x = r0.x + r1.x;
    out.y = r0.y + r1.y;
    out.z = r2.x + r3.x;
    out.w = r2.y + r3.y;
    *reinterpret_cast<float4*>(dst + (size_t)n * D + ql * 4) = out;
}

// ---------------- quadgemm: dst[n,:] = relu( sum_m h_m[n,:] @ W4[m]  + bias ) ------
__global__ __launch_bounds__(256, 2)
void quadgemm_kernel(float* __restrict__ dst,
                     const float* __restrict__ h0, const float* __restrict__ h1,
                     const float* __restrict__ h2, const float* __restrict__ h3,
                     const float* __restrict__ W4, const float* __restrict__ bias,
                     int N)
{
    __shared__ __align__(16) float Ws[4 * D * D];   // 16 KB
    __shared__ float Bs[D];
    int t = threadIdx.x;
#pragma unroll
    for (int q = 0; q < 4; q++)
        reinterpret_cast<float4*>(Ws)[q * 256 + t] =
            reinterpret_cast<const float4*>(W4)[q * 256 + t];
    if (t < D) Bs[t] = bias[t];
    __syncthreads();

    int n = blockIdx.x * 256 + t;
    if (n >= N) return;

    unsigned long long acc[D / 2];
#pragma unroll
    for (int j = 0; j < D / 2; j++) acc[j] = 0ull;

    const float* hs[4] = { h0, h1, h2, h3 };

#pragma unroll
    for (int m = 0; m < 4; m++) {
        float h[D];
        const float4* hr = reinterpret_cast<const float4*>(hs[m] + (size_t)n * D);
#pragma unroll
        for (int q = 0; q < 8; q++) {
            float4 v = __ldg(hr + q);
            h[q*4] = v.x; h[q*4+1] = v.y; h[q*4+2] = v.z; h[q*4+3] = v.w;
        }
        const ulonglong2* Wm = reinterpret_cast<const ulonglong2*>(Ws + m * D * D);
#pragma unroll
        for (int i = 0; i < D; i++) {
            unsigned long long hv = pack2(h[i], h[i]);
            const ulonglong2* wr = Wm + i * 8;
#pragma unroll
            for (int j = 0; j < 8; j++) {
                ulonglong2 w = wr[j];
                fma2(acc[j*2],     hv, w.x);
                fma2(acc[j*2 + 1], hv, w.y);
            }
        }
    }

    float* drow = dst + (size_t)n * D;
#pragma unroll
    for (int j2 = 0; j2 < D / 4; j2++) {
        float2 a = unpack2(acc[j2*2]);
        float2 b = unpack2(acc[j2*2 + 1]);
        float4 o;
        o.x = fmaxf(a.x + Bs[j2*4],     0.0f);
        o.y = fmaxf(a.y + Bs[j2*4 + 1], 0.0f);
        o.z = fmaxf(b.x + Bs[j2*4 + 2], 0.0f);
        o.w = fmaxf(b.y + Bs[j2*4 + 3], 0.0f);
        reinterpret_cast<float4*>(drow)[j2] = o;
    }
}

// ---------------- launch ----------------

extern "C" void kernel_launch(void* const* d_in, const int* in_sizes, int n_in,
                              void* d_out, int out_size)
{
    const float* x  = (const float*)d_in[0];
    const int*   ei = (const int*)d_in[1];
    const float* ew = (const float*)d_in[2];
    const float* W  = (const float*)d_in[3];
    const float* b  = (const float*)d_in[4];

    const int N = in_sizes[0] / D;
    const int E = in_sizes[2];

    const int* row = ei;
    const int* col = ei + E;

    float* tmp3_p;  cudaGetSymbolAddress((void**)&tmp3_p,  g_tmp3);
    void*  scan_p;  cudaGetSymbolAddress(&scan_p,          g_scanstate);
    float* g1_p;    cudaGetSymbolAddress((void**)&g1_p,    g_g1);
    float* g2_p;    cudaGetSymbolAddress((void**)&g2_p,    g_g2);
    float* g3_p;    cudaGetSymbolAddress((void**)&g3_p,    g_g3);
    float* x_p;     cudaGetSymbolAddress((void**)&x_p,     g_x);

    const int TB = 256;
    const int eb = (E + TB - 1) / TB;
    const int scan_blocks = (N + SCAN_B - 1) / SCAN_B;

    // ---- CSR + norm build ----
    cudaMemsetAsync(tmp3_p, 0, (size_t)3 * N * sizeof(float));
    cudaMemsetAsync(scan_p, 0, 256 * sizeof(unsigned long long));
    deg_kernel<<<eb, TB>>>(col, ew, E);
    scanfused_kernel<<<scan_blocks, SCAN_B>>>(N, E);
    fill_kernel<<<eb, TB>>>(row, col, ew, E);

    const int qg_blocks     = (N + 255) / 256;
    // 4 nodes per warp -> N/4 warps -> N*8 threads
    const int gather_blocks = (N * 8 + TB - 1) / TB;

    const float* xcur = x;
    for (int l = 0; l < LAYERS; l++) {
        const float* Wl = W + (size_t)l * (HOPS + 1) * D * D;

        // power form: g1 = A x, g2 = A g1, g3 = A g2
        gather_kernel<<<gather_blocks, TB>>>(g1_p, xcur, N);
        gather_kernel<<<gather_blocks, TB>>>(g2_p, g1_p, N);
        gather_kernel<<<gather_blocks, TB>>>(g3_p, g2_p, N);

        float* dst = (l == LAYERS - 1) ? (float*)d_out : x_p;
        // x' = relu(x W0 + g1 W1 + g2 W2 + g3 W3 + b)
        quadgemm_kernel<<<qg_blocks, 256>>>(dst, xcur, g1_p, g2_p, g3_p,
                                            Wl, b + (size_t)l * D, N);
        xcur = x_p;
    }
}